// round 2
// baseline (speedup 1.0000x reference)
#include <cuda_runtime.h>
#include <cuda_bf16.h>
#include <math.h>

// ---------------- problem constants ----------------
#define NB    8          // batch
#define CCH   640        // channels
#define HW    1024       // 32*32
#define NTOK  (NB*HW)    // 8192 tokens
#define NH    8          // heads
#define DH    80         // head dim
#define SCTX  77         // context length
#define DCTX  512
#define FF    5120       // lin1 out
#define FFH   2560
#define GRP   32
#define CPG   (CCH/GRP)  // 20

// ---------------- scratch (static device memory; no cudaMalloc allowed) ----
__device__ float g_X [ (long)NTOK * CCH ];          // running x  [8192,640]
__device__ float g_A [ (long)NTOK * FF  ];          // qkv / lin1 out [8192,5120]
__device__ float g_B [ (long)NTOK * FFH ];          // ln out / attn out / geglu [8192,2560]
__device__ float g_S [ (long)NB * NH * HW * HW ];   // scores [8,8,1024,1024]
__device__ float g_CK[ (long)NB * SCTX * CCH ];
__device__ float g_CV[ (long)NB * SCTX * CCH ];
__device__ float g_GS[ NB * GRP * 2 ];              // groupnorm mean/rstd

// ================= GroupNorm stats =================
__global__ void gn_stats_k(const float* __restrict__ x, float* __restrict__ st) {
    // block = (n,g); elements are contiguous: 20 channels * 1024 hw
    int n = blockIdx.x >> 5, g = blockIdx.x & 31;
    const float* base = x + ((long)n * CCH + g * CPG) * HW;
    const int CNT = CPG * HW; // 20480
    float s = 0.f, s2 = 0.f;
    for (int i = threadIdx.x; i < CNT; i += 256) {
        float v = base[i]; s += v; s2 += v * v;
    }
    __shared__ float r1[256], r2[256];
    r1[threadIdx.x] = s; r2[threadIdx.x] = s2; __syncthreads();
    for (int st_ = 128; st_ > 0; st_ >>= 1) {
        if (threadIdx.x < st_) { r1[threadIdx.x] += r1[threadIdx.x + st_]; r2[threadIdx.x] += r2[threadIdx.x + st_]; }
        __syncthreads();
    }
    if (threadIdx.x == 0) {
        float mean = r1[0] / (float)CNT;
        float var  = r2[0] / (float)CNT - mean * mean;
        st[blockIdx.x * 2]     = mean;
        st[blockIdx.x * 2 + 1] = rsqrtf(var + 1e-6f);
    }
}

// ======== GroupNorm apply + transpose [n,c,hw] -> [token, c] ========
__global__ void gn_apply_t_k(const float* __restrict__ x, const float* __restrict__ st,
                             const float* __restrict__ gs, const float* __restrict__ gb,
                             float* __restrict__ out) {
    __shared__ float tile[32][33];
    int n = blockIdx.z, c0 = blockIdx.y * 32, hw0 = blockIdx.x * 32;
    int tx = threadIdx.x, ty = threadIdx.y;
#pragma unroll
    for (int j = 0; j < 4; j++) {
        int c = c0 + ty + j * 8;
        float v = x[((long)n * CCH + c) * HW + hw0 + tx];
        int g = c / CPG;
        float mu = st[(n * GRP + g) * 2], r = st[(n * GRP + g) * 2 + 1];
        tile[ty + j * 8][tx] = (v - mu) * r * gs[c] + gb[c];
    }
    __syncthreads();
#pragma unroll
    for (int j = 0; j < 4; j++) {
        int hw = hw0 + ty + j * 8;
        out[((long)n * HW + hw) * CCH + c0 + tx] = tile[tx][ty + j * 8];
    }
}

// ================= LayerNorm (row = token, width 640) =================
__global__ void layernorm_k(const float* __restrict__ X, const float* __restrict__ s,
                            const float* __restrict__ b, float* __restrict__ O) {
    long row = blockIdx.x;
    const float* p = X + row * CCH;
    int tid = threadIdx.x;
    float v[3]; int cnt = 0;
    float sm = 0.f, s2 = 0.f;
    for (int i = tid; i < CCH; i += 256) { float t = p[i]; v[cnt++] = t; sm += t; s2 += t * t; }
    __shared__ float r1[256], r2[256];
    r1[tid] = sm; r2[tid] = s2; __syncthreads();
    for (int st = 128; st > 0; st >>= 1) {
        if (tid < st) { r1[tid] += r1[tid + st]; r2[tid] += r2[tid + st]; }
        __syncthreads();
    }
    float mean = r1[0] / (float)CCH;
    float var  = r2[0] / (float)CCH - mean * mean;
    float rstd = rsqrtf(var + 1e-5f);
    cnt = 0;
    for (int i = tid; i < CCH; i += 256)
        O[row * CCH + i] = (v[cnt++] - mean) * rstd * s[i] + b[i];
}

// ================= big GEMM: C[M,N] = A[M,K] @ op(B) (+bias)(+res) =======
// BT=false: B is [K,N] row-major (w[in,out]).  BT=true: B is [N,K] (w[out,in]).
// permute: write C as [n, o, hw] (token m -> n=m>>10, hw=m&1023); res read at same index.
template<bool BT>
__global__ __launch_bounds__(256) void gemm_big(
    const float* __restrict__ A, const float* __restrict__ B,
    const float* __restrict__ bias, const float* __restrict__ res,
    float* __restrict__ C, int M, int N, int K, int permute) {
    __shared__ float As[16][132];
    __shared__ float Bs[16][68];
    int tid = threadIdx.x;
    int m0 = blockIdx.y * 128, n0 = blockIdx.x * 64;
    int ty = tid >> 4, tx = tid & 15;      // 16x16 thread grid; 8x4 micro-tile
    float acc[8][4] = {};
    for (int k0 = 0; k0 < K; k0 += 16) {
#pragma unroll
        for (int i = 0; i < 8; i++) {       // A tile 128x16
            int lin = tid + i * 256;
            int m = lin >> 4, k = lin & 15;
            float v = 0.f;
            int gm = m0 + m;
            if (gm < M && k0 + k < K) v = A[(long)gm * K + k0 + k];
            As[k][m] = v;
        }
#pragma unroll
        for (int i = 0; i < 4; i++) {       // B tile 16x64
            int lin = tid + i * 256;
            float v = 0.f;
            if (BT) {
                int n = lin >> 4, k = lin & 15;
                int gn = n0 + n;
                if (gn < N && k0 + k < K) v = B[(long)gn * K + k0 + k];
                Bs[k][n] = v;
            } else {
                int k = lin >> 6, n = lin & 63;
                int gn = n0 + n;
                if (gn < N && k0 + k < K) v = B[(long)(k0 + k) * N + gn];
                Bs[k][n] = v;
            }
        }
        __syncthreads();
#pragma unroll
        for (int k = 0; k < 16; k++) {
            float4 a0 = *(const float4*)&As[k][ty * 8];
            float4 a1 = *(const float4*)&As[k][ty * 8 + 4];
            float4 bb = *(const float4*)&Bs[k][tx * 4];
            float a[8] = {a0.x,a0.y,a0.z,a0.w,a1.x,a1.y,a1.z,a1.w};
            float b[4] = {bb.x,bb.y,bb.z,bb.w};
#pragma unroll
            for (int i = 0; i < 8; i++)
#pragma unroll
                for (int j = 0; j < 4; j++) acc[i][j] = fmaf(a[i], b[j], acc[i][j]);
        }
        __syncthreads();
    }
#pragma unroll
    for (int i = 0; i < 8; i++) {
        int gm = m0 + ty * 8 + i;
        if (gm >= M) continue;
#pragma unroll
        for (int j = 0; j < 4; j++) {
            int gn = n0 + tx * 4 + j;
            if (gn >= N) continue;
            float v = acc[i][j];
            if (bias) v += bias[gn];
            long idx;
            if (!permute) idx = (long)gm * N + gn;
            else          idx = ((long)(gm >> 10) * CCH + gn) * HW + (gm & 1023);
            if (res) v += res[idx];
            C[idx] = v;
        }
    }
}

// ========== batched GEMM over z=b*NH+h : C = alpha * A @ op(B) ==========
template<bool BT>
__global__ __launch_bounds__(256) void bgemm(
    const float* __restrict__ Ab, const float* __restrict__ Bb, float* __restrict__ Cb,
    int M, int N, int Kd, int lda, int ldb, int ldc,
    long aB, long aH, long bB, long bH, long cB, long cH, float alpha) {
    int z = blockIdx.z, b = z >> 3, h = z & 7;
    const float* A = Ab + b * aB + h * aH;
    const float* B = Bb + b * bB + h * bH;
    float* C = Cb + b * cB + h * cH;
    __shared__ float As[16][68];
    __shared__ float Bs[16][68];
    int tid = threadIdx.x;
    int m0 = blockIdx.y * 64, n0 = blockIdx.x * 64;
    int ty = tid >> 4, tx = tid & 15;      // 4x4 micro-tile
    float acc[4][4] = {};
    for (int k0 = 0; k0 < Kd; k0 += 16) {
#pragma unroll
        for (int i = 0; i < 4; i++) {       // A tile 64x16
            int lin = tid + i * 256;
            int m = lin >> 4, k = lin & 15;
            float v = 0.f;
            if (m0 + m < M && k0 + k < Kd) v = A[(long)(m0 + m) * lda + k0 + k];
            As[k][m] = v;
        }
#pragma unroll
        for (int i = 0; i < 4; i++) {       // B tile 16x64
            int lin = tid + i * 256;
            float v = 0.f;
            if (BT) {
                int n = lin >> 4, k = lin & 15;
                if (n0 + n < N && k0 + k < Kd) v = B[(long)(n0 + n) * ldb + k0 + k];
                Bs[k][n] = v;
            } else {
                int k = lin >> 6, n = lin & 63;
                if (n0 + n < N && k0 + k < Kd) v = B[(long)(k0 + k) * ldb + n0 + n];
                Bs[k][n] = v;
            }
        }
        __syncthreads();
#pragma unroll
        for (int k = 0; k < 16; k++) {
            float4 av = *(const float4*)&As[k][ty * 4];
            float4 bv = *(const float4*)&Bs[k][tx * 4];
            float a[4] = {av.x,av.y,av.z,av.w};
            float b2[4] = {bv.x,bv.y,bv.z,bv.w};
#pragma unroll
            for (int i = 0; i < 4; i++)
#pragma unroll
                for (int j = 0; j < 4; j++) acc[i][j] = fmaf(a[i], b2[j], acc[i][j]);
        }
        __syncthreads();
    }
#pragma unroll
    for (int i = 0; i < 4; i++) {
        int gm = m0 + ty * 4 + i;
        if (gm >= M) continue;
#pragma unroll
        for (int j = 0; j < 4; j++) {
            int gn = n0 + tx * 4 + j;
            if (gn >= N) continue;
            C[(long)gm * ldc + gn] = alpha * acc[i][j];
        }
    }
}

// ================= row softmax =================
__global__ void softmax_k(float* __restrict__ S, int L) {
    __shared__ float red[128];
    long row = blockIdx.x;
    float* p = S + row * (long)L;
    int tid = threadIdx.x;
    float v[8]; int cnt = 0;
    float mx = -1e30f;
    for (int i = tid; i < L; i += 128) { float t = p[i]; v[cnt++] = t; mx = fmaxf(mx, t); }
    red[tid] = mx; __syncthreads();
    for (int s = 64; s > 0; s >>= 1) { if (tid < s) red[tid] = fmaxf(red[tid], red[tid + s]); __syncthreads(); }
    mx = red[0]; __syncthreads();
    float sum = 0.f;
    for (int c = 0; c < cnt; c++) { v[c] = expf(v[c] - mx); sum += v[c]; }
    red[tid] = sum; __syncthreads();
    for (int s = 64; s > 0; s >>= 1) { if (tid < s) red[tid] += red[tid + s]; __syncthreads(); }
    float inv = 1.f / red[0];
    cnt = 0;
    for (int i = tid; i < L; i += 128) p[i] = v[cnt++] * inv;
}

// ================= GeGLU: out = a * gelu_exact(gate) =================
__global__ void geglu_k(const float* __restrict__ A, float* __restrict__ O) {
    long i = (long)blockIdx.x * 256 + threadIdx.x;
    if (i >= (long)NTOK * FFH) return;
    long row = i / FFH; int col = (int)(i % FFH);
    float a = A[row * FF + col];
    float g = A[row * FF + FFH + col];
    O[i] = a * (0.5f * g * (1.0f + erff(g * 0.70710678118654752f)));
}

// =========================================================================
extern "C" void kernel_launch(void* const* d_in, const int* in_sizes, int n_in,
                              void* d_out, int out_size) {
    const float* x       = (const float*)d_in[0];
    const float* ctx     = (const float*)d_in[1];
    const float* gn_s    = (const float*)d_in[2];
    const float* gn_b    = (const float*)d_in[3];
    const float* conv1_w = (const float*)d_in[4];
    const float* conv1_b = (const float*)d_in[5];
    const float* ln1_s   = (const float*)d_in[6];
    const float* ln1_b   = (const float*)d_in[7];
    const float* sa_in_w = (const float*)d_in[8];
    const float* sa_out_w= (const float*)d_in[9];
    const float* sa_out_b= (const float*)d_in[10];
    const float* ln2_s   = (const float*)d_in[11];
    const float* ln2_b   = (const float*)d_in[12];
    const float* ca_q_w  = (const float*)d_in[13];
    const float* ca_k_w  = (const float*)d_in[14];
    const float* ca_v_w  = (const float*)d_in[15];
    const float* ca_out_w= (const float*)d_in[16];
    const float* ca_out_b= (const float*)d_in[17];
    const float* ln3_s   = (const float*)d_in[18];
    const float* ln3_b   = (const float*)d_in[19];
    const float* lin1_w  = (const float*)d_in[20];
    const float* lin1_b  = (const float*)d_in[21];
    const float* lin2_w  = (const float*)d_in[22];
    const float* lin2_b  = (const float*)d_in[23];
    const float* co_w    = (const float*)d_in[24];
    const float* co_b    = (const float*)d_in[25];
    float* out = (float*)d_out;

    float *pX, *pA, *pB, *pS, *pCK, *pCV, *pGS;
    cudaGetSymbolAddress((void**)&pX,  g_X);
    cudaGetSymbolAddress((void**)&pA,  g_A);
    cudaGetSymbolAddress((void**)&pB,  g_B);
    cudaGetSymbolAddress((void**)&pS,  g_S);
    cudaGetSymbolAddress((void**)&pCK, g_CK);
    cudaGetSymbolAddress((void**)&pCV, g_CV);
    cudaGetSymbolAddress((void**)&pGS, g_GS);

    const float ISQ = 0.11180339887498949f; // 1/sqrt(80)

    // 1) GroupNorm -> token-major (into g_B first 640 cols packed)
    gn_stats_k<<<NB * GRP, 256>>>(x, pGS);
    gn_apply_t_k<<<dim3(32, 20, NB), dim3(32, 8)>>>(x, pGS, gn_s, gn_b, pB);

    // 2) conv1: X = XN @ conv1_w^T + b      (conv1_w is [out,in] -> BT)
    gemm_big<true><<<dim3(CCH / 64, NTOK / 128), 256>>>(pB, conv1_w, conv1_b, nullptr, pX, NTOK, CCH, CCH, 0);

    // 3) self-attention
    layernorm_k<<<NTOK, 256>>>(pX, ln1_s, ln1_b, pB);
    gemm_big<false><<<dim3(3 * CCH / 64, NTOK / 128), 256>>>(pB, sa_in_w, nullptr, nullptr, pA, NTOK, 3 * CCH, CCH, 0);
    // scores = Q K^T / sqrt(dh)
    bgemm<true><<<dim3(16, 16, NB * NH), 256>>>(
        pA, pA + CCH, pS, HW, HW, DH, 3 * CCH, 3 * CCH, HW,
        (long)HW * 3 * CCH, DH, (long)HW * 3 * CCH, DH, (long)NH * HW * HW, (long)HW * HW, ISQ);
    softmax_k<<<NB * NH * HW, 128>>>(pS, HW);
    // O = P V
    bgemm<false><<<dim3(2, 16, NB * NH), 256>>>(
        pS, pA + 2 * CCH, pB, HW, DH, HW, HW, 3 * CCH, CCH,
        (long)NH * HW * HW, (long)HW * HW, (long)HW * 3 * CCH, DH, (long)HW * CCH, DH, 1.0f);
    gemm_big<false><<<dim3(CCH / 64, NTOK / 128), 256>>>(pB, sa_out_w, sa_out_b, pX, pX, NTOK, CCH, CCH, 0);

    // 4) cross-attention
    layernorm_k<<<NTOK, 256>>>(pX, ln2_s, ln2_b, pB);
    gemm_big<false><<<dim3(CCH / 64, NTOK / 128), 256>>>(pB, ca_q_w, nullptr, nullptr, pA, NTOK, CCH, CCH, 0);
    gemm_big<false><<<dim3(CCH / 64, (NB * SCTX + 127) / 128), 256>>>(ctx, ca_k_w, nullptr, nullptr, pCK, NB * SCTX, CCH, DCTX, 0);
    gemm_big<false><<<dim3(CCH / 64, (NB * SCTX + 127) / 128), 256>>>(ctx, ca_v_w, nullptr, nullptr, pCV, NB * SCTX, CCH, DCTX, 0);
    bgemm<true><<<dim3(2, 16, NB * NH), 256>>>(
        pA, pCK, pS, HW, SCTX, DH, CCH, CCH, SCTX,
        (long)HW * CCH, DH, (long)SCTX * CCH, DH, (long)NH * HW * SCTX, (long)HW * SCTX, ISQ);
    softmax_k<<<NB * NH * HW, 128>>>(pS, SCTX);
    bgemm<false><<<dim3(2, 16, NB * NH), 256>>>(
        pS, pCV, pB, HW, DH, SCTX, SCTX, CCH, CCH,
        (long)NH * HW * SCTX, (long)HW * SCTX, (long)SCTX * CCH, DH, (long)HW * CCH, DH, 1.0f);
    gemm_big<false><<<dim3(CCH / 64, NTOK / 128), 256>>>(pB, ca_out_w, ca_out_b, pX, pX, NTOK, CCH, CCH, 0);

    // 5) GeGLU FFN
    layernorm_k<<<NTOK, 256>>>(pX, ln3_s, ln3_b, pB);
    gemm_big<false><<<dim3(FF / 64, NTOK / 128), 256>>>(pB, lin1_w, lin1_b, nullptr, pA, NTOK, FF, CCH, 0);
    geglu_k<<<(int)(((long)NTOK * FFH + 255) / 256), 256>>>(pA, pB);
    gemm_big<false><<<dim3(CCH / 64, NTOK / 128), 256>>>(pB, lin2_w, lin2_b, pX, pX, NTOK, CCH, FFH, 0);

    // 6) final conv + long residual, written as [n, c, h, w]
    gemm_big<true><<<dim3(CCH / 64, NTOK / 128), 256>>>(pX, co_w, co_b, x, out, NTOK, CCH, CCH, 1);
}